// round 8
// baseline (speedup 1.0000x reference)
#include <cuda_runtime.h>
#include <cuda_bf16.h>
#include <cstdint>

#define NROWS 200000
#define NTILES 3125          // 200000 / 64
#define BM 64
#define LDIM 480

// ============================ HMMA helpers ============================
__device__ __forceinline__ void mma_bf16(float& c0, float& c1, float& c2, float& c3,
                                         uint32_t a0, uint32_t a1, uint32_t a2, uint32_t a3,
                                         uint32_t b0, uint32_t b1)
{
    asm volatile("mma.sync.aligned.m16n8k16.row.col.f32.bf16.bf16.f32 "
                 "{%0,%1,%2,%3}, {%4,%5,%6,%7}, {%8,%9}, {%0,%1,%2,%3};"
                 : "+f"(c0), "+f"(c1), "+f"(c2), "+f"(c3)
                 : "r"(a0), "r"(a1), "r"(a2), "r"(a3), "r"(b0), "r"(b1));
}

__device__ __forceinline__ uint32_t pack_hi(float x, float y, float& rx, float& ry) {
    __nv_bfloat162 h = __float22bfloat162_rn(make_float2(x, y));
    float2 hf = __bfloat1622float2(h);
    rx = x - hf.x; ry = y - hf.y;
    return *(uint32_t*)&h;
}
__device__ __forceinline__ uint32_t pack_lo(float rx, float ry) {
    __nv_bfloat162 l = __float22bfloat162_rn(make_float2(rx, ry));
    return *(uint32_t*)&l;
}
__device__ __forceinline__ void split_bf16(float v, __nv_bfloat16& h, __nv_bfloat16& l) {
    h = __float2bfloat16(v);
    l = __float2bfloat16(v - __bfloat162float(h));
}
__device__ __forceinline__ void split4(const float* f, uint2& hi, uint2& lo) {
    float r0, r1, r2, r3;
    uint32_t h0 = pack_hi(f[0], f[1], r0, r1);
    uint32_t h1 = pack_hi(f[2], f[3], r2, r3);
    hi = make_uint2(h0, h1);
    lo = make_uint2(pack_lo(r0, r1), pack_lo(r2, r3));
}

// ============================================================================
// Kernel 0 (HMMA, ks-outer + interleaved hi/lo B): out[:, 0:128]
// smem: b0s[0,512) B_il[512,70144) {u32 hi, u32 lo} per (n, kpair), row stride
// 68 uint2 (544B); AH[70144,87552) AL[87552,104960) bf16 stride 136.
// Per-thread LDS per tile: 64 A LDS.32 + 128 B LDS.64 (was 320 LDS.32).
// ============================================================================
#define K0_STRIDE 136
#define K0_B0   0
#define K0_BIL  512
#define K0_BROW 68            // uint2 per B row
#define K0_AH   70144
#define K0_AL   87552
#define K0_SMEM 104960

__global__ void __launch_bounds__(256, 2)
k0_mma(const float* __restrict__ x, const float* __restrict__ w0,
       const float* __restrict__ b0, float* __restrict__ out)
{
    extern __shared__ char smem[];
    float* b0s = (float*)(smem + K0_B0);
    uint2* bil = (uint2*)(smem + K0_BIL);

    const int tid  = threadIdx.x;
    const int wid  = tid >> 5;
    const int lane = tid & 31;
    const float a0 = 0.08838834764831845f;   // 1/sqrt(128)

    // stage B interleaved: (n, kp) -> {hi(2kp,2kp+1), lo(2kp,2kp+1)}
    for (int idx = tid; idx < 128 * 64; idx += 256) {
        int n = idx & 127, kp = idx >> 7;
        float v0 = a0 * w0[(2 * kp) * 128 + n];
        float v1 = a0 * w0[(2 * kp + 1) * 128 + n];
        float r0, r1;
        uint32_t hi = pack_hi(v0, v1, r0, r1);
        uint32_t lo = pack_lo(r0, r1);
        bil[n * K0_BROW + kp] = make_uint2(hi, lo);
    }
    if (tid < 128) b0s[tid] = b0[tid];

    const int mt = wid >> 1;
    const int nh = wid & 1;
    const int ar = mt * 16 + (lane >> 2);
    const int ak = (lane & 3) * 2;
    const int bn = nh * 64 + (lane >> 2);
    const int kq = lane & 3;                 // k-pair within ks group
    const int ncol = nh * 64 + (lane & 3) * 2;

    __syncthreads();

    for (int t = blockIdx.x; t < NTILES; t += gridDim.x) {
        const int row0 = t * BM;

        #pragma unroll
        for (int i = tid; i < 64 * 32; i += 256) {
            int r = i >> 5, c4 = (i & 31) << 2;
            float4 v = *(const float4*)(x + (size_t)(row0 + r) * LDIM + c4);
            float rx, ry, rz, rw;
            uint32_t h0 = pack_hi(v.x, v.y, rx, ry);
            uint32_t h1 = pack_hi(v.z, v.w, rz, rw);
            uint32_t l0 = pack_lo(rx, ry);
            uint32_t l1 = pack_lo(rz, rw);
            uint32_t off = (uint32_t)(r * K0_STRIDE + c4) * 2u;
            *(uint2*)(smem + K0_AH + off) = make_uint2(h0, h1);
            *(uint2*)(smem + K0_AL + off) = make_uint2(l0, l1);
        }
        __syncthreads();

        // accumulators initialized with bias
        float C[8][4];
        #pragma unroll
        for (int nt = 0; nt < 8; nt++) {
            float bias0 = b0s[ncol + nt * 8];
            float bias1 = b0s[ncol + nt * 8 + 1];
            C[nt][0] = bias0; C[nt][1] = bias1;
            C[nt][2] = bias0; C[nt][3] = bias1;
        }

        const uint32_t abase = (uint32_t)(ar * K0_STRIDE + ak) * 2u;
        #pragma unroll
        for (int ks = 0; ks < 8; ks++) {
            // A fragments for this ks only (8 regs)
            uint32_t o = abase + (uint32_t)(ks * 16) * 2u;
            uint32_t ah0 = *(const uint32_t*)(smem + K0_AH + o);
            uint32_t ah1 = *(const uint32_t*)(smem + K0_AH + o + 8 * K0_STRIDE * 2);
            uint32_t ah2 = *(const uint32_t*)(smem + K0_AH + o + 16);
            uint32_t ah3 = *(const uint32_t*)(smem + K0_AH + o + 8 * K0_STRIDE * 2 + 16);
            uint32_t al0 = *(const uint32_t*)(smem + K0_AL + o);
            uint32_t al1 = *(const uint32_t*)(smem + K0_AL + o + 8 * K0_STRIDE * 2);
            uint32_t al2 = *(const uint32_t*)(smem + K0_AL + o + 16);
            uint32_t al3 = *(const uint32_t*)(smem + K0_AL + o + 8 * K0_STRIDE * 2 + 16);

            const int kpb = ks * 8 + kq;
            #pragma unroll
            for (int nt = 0; nt < 8; nt++) {
                const uint2* brow = bil + (bn + nt * 8) * K0_BROW;
                uint2 bv0 = brow[kpb];        // {bh0, bl0}
                uint2 bv1 = brow[kpb + 4];    // {bh1, bl1}
                mma_bf16(C[nt][0], C[nt][1], C[nt][2], C[nt][3],
                         ah0, ah1, ah2, ah3, bv0.x, bv1.x);
                mma_bf16(C[nt][0], C[nt][1], C[nt][2], C[nt][3],
                         al0, al1, al2, al3, bv0.x, bv1.x);
                mma_bf16(C[nt][0], C[nt][1], C[nt][2], C[nt][3],
                         ah0, ah1, ah2, ah3, bv0.y, bv1.y);
            }
        }

        const int grow = row0 + mt * 16 + (lane >> 2);
        #pragma unroll
        for (int nt = 0; nt < 8; nt++) {
            float* o0 = out + (size_t)grow * LDIM + ncol + nt * 8;
            *(float2*)o0              = make_float2(C[nt][0], C[nt][1]);
            *(float2*)(o0 + 8 * LDIM) = make_float2(C[nt][2], C[nt][3]);
        }
        __syncthreads();
    }
}

// ============================================================================
// Kernel 1 (unchanged from R7 passing): out[:, 128+3w+i]
// ============================================================================
#define K1_ST 72
#define K1_BH 0
#define K1_BL 9216
#define K1_AH 18432
#define K1_AL 46080
#define K1_ABLK 9216
#define K1_OUT 18432          // overlay on Ah/Al
#define K1_OST 196
#define K1_SMEM 73728

__global__ void __launch_bounds__(256, 2)
k1_mma(const float* __restrict__ x, const float* __restrict__ w1,
       float* __restrict__ out)
{
    extern __shared__ char smem[];
    const int tid  = threadIdx.x;
    const int wid  = tid >> 5;
    const int lane = tid & 31;
    const float a1 = 0.125f;   // 1/sqrt(64)

    for (int idx = tid; idx < 64 * 64; idx += 256) {
        int u = idx >> 6, w = idx & 63;
        float v = a1 * w1[idx];
        __nv_bfloat16 h, l;
        split_bf16(v, h, l);
        *(__nv_bfloat16*)(smem + K1_BH + (w * K1_ST + u) * 2) = h;
        *(__nv_bfloat16*)(smem + K1_BL + (w * K1_ST + u) * 2) = l;
    }

    const int mt = wid >> 1;
    const int nh = wid & 1;
    const int ar = mt * 16 + (lane >> 2);
    const int ak = (lane & 3) * 2;
    const int bn = lane >> 2;
    const int np = (lane & 3) * 2;

    for (int t = blockIdx.x; t < NTILES; t += gridDim.x) {
        const int row0 = t * BM;
        __syncthreads();

        #pragma unroll
        for (int it = 0; it < 4; it++) {
            int i = tid + it * 256;
            int r = i >> 4, g = i & 15;
            const float* xp = x + (size_t)(row0 + r) * LDIM + 128 + g * 12;
            float f[12];
            *(float4*)(f)     = *(const float4*)(xp);
            *(float4*)(f + 4) = *(const float4*)(xp + 4);
            *(float4*)(f + 8) = *(const float4*)(xp + 8);
            #pragma unroll
            for (int ch = 0; ch < 3; ch++) {
                float g4[4] = {f[ch], f[ch + 3], f[ch + 6], f[ch + 9]};
                uint2 hi, lo;
                split4(g4, hi, lo);
                uint32_t o = (uint32_t)(ch * K1_ABLK) + (uint32_t)(r * K1_ST + 4 * g) * 2u;
                *(uint2*)(smem + K1_AH + o) = hi;
                *(uint2*)(smem + K1_AL + o) = lo;
            }
        }
        __syncthreads();

        float C[3][4][4];
        #pragma unroll
        for (int ch = 0; ch < 3; ch++) {
            const uint32_t abase = (uint32_t)(ch * K1_ABLK) + (uint32_t)(ar * K1_ST + ak) * 2u;
            uint32_t ah[4][4], al[4][4];
            #pragma unroll
            for (int ks = 0; ks < 4; ks++) {
                uint32_t o = abase + (uint32_t)(ks * 16) * 2u;
                ah[ks][0] = *(const uint32_t*)(smem + K1_AH + o);
                ah[ks][1] = *(const uint32_t*)(smem + K1_AH + o + 8 * K1_ST * 2);
                ah[ks][2] = *(const uint32_t*)(smem + K1_AH + o + 16);
                ah[ks][3] = *(const uint32_t*)(smem + K1_AH + o + 8 * K1_ST * 2 + 16);
                al[ks][0] = *(const uint32_t*)(smem + K1_AL + o);
                al[ks][1] = *(const uint32_t*)(smem + K1_AL + o + 8 * K1_ST * 2);
                al[ks][2] = *(const uint32_t*)(smem + K1_AL + o + 16);
                al[ks][3] = *(const uint32_t*)(smem + K1_AL + o + 8 * K1_ST * 2 + 16);
            }
            #pragma unroll
            for (int q = 0; q < 4; q++) {
                const int nt = nh * 4 + q;
                float p0 = 0.f, p1 = 0.f, p2 = 0.f, p3 = 0.f;
                float q0 = 0.f, q1 = 0.f, q2 = 0.f, q3 = 0.f;
                float s0 = 0.f, s1 = 0.f, s2 = 0.f, s3 = 0.f;
                const uint32_t bbase = (uint32_t)((bn + nt * 8) * K1_ST + ak) * 2u;
                #pragma unroll
                for (int ks = 0; ks < 4; ks++) {
                    uint32_t o = bbase + (uint32_t)(ks * 16) * 2u;
                    uint32_t bh0 = *(const uint32_t*)(smem + K1_BH + o);
                    uint32_t bh1 = *(const uint32_t*)(smem + K1_BH + o + 16);
                    uint32_t bl0 = *(const uint32_t*)(smem + K1_BL + o);
                    uint32_t bl1 = *(const uint32_t*)(smem + K1_BL + o + 16);
                    mma_bf16(p0, p1, p2, p3, ah[ks][0], ah[ks][1], ah[ks][2], ah[ks][3], bh0, bh1);
                    mma_bf16(q0, q1, q2, q3, al[ks][0], al[ks][1], al[ks][2], al[ks][3], bh0, bh1);
                    mma_bf16(s0, s1, s2, s3, ah[ks][0], ah[ks][1], ah[ks][2], ah[ks][3], bl0, bl1);
                }
                C[ch][q][0] = p0 + q0 + s0;
                C[ch][q][1] = p1 + q1 + s1;
                C[ch][q][2] = p2 + q2 + s2;
                C[ch][q][3] = p3 + q3 + s3;
            }
        }
        __syncthreads();

        {
            float* st = (float*)(smem + K1_OUT);
            const int rA = mt * 16 + (lane >> 2);
            #pragma unroll
            for (int ch = 0; ch < 3; ch++) {
                #pragma unroll
                for (int q = 0; q < 4; q++) {
                    const int n0 = (nh * 4 + q) * 8 + np;
                    const int col = 3 * n0 + ch;
                    st[rA * K1_OST + col]           = C[ch][q][0];
                    st[rA * K1_OST + col + 3]       = C[ch][q][1];
                    st[(rA + 8) * K1_OST + col]     = C[ch][q][2];
                    st[(rA + 8) * K1_OST + col + 3] = C[ch][q][3];
                }
            }
        }
        __syncthreads();

        {
            const float* st = (const float*)(smem + K1_OUT);
            #pragma unroll
            for (int it = 0; it < 12; it++) {
                int i = tid + it * 256;
                int r = i / 48, c4 = (i - r * 48) * 4;
                float4 v = *(const float4*)(st + r * K1_OST + c4);
                *(float4*)(out + (size_t)(row0 + r) * LDIM + 128 + c4) = v;
            }
        }
    }
}

// ============================================================================
// Kernel 2 (unchanged from R7 passing): out[:, 320+5w+i]
// ============================================================================
#define K2_ST 40
#define K2_BH 0
#define K2_BL 2560
#define K2_AH 5120
#define K2_AL 30720
#define K2_ABLK 5120
#define K2_OUT 56320
#define K2_OST 164
#define K2_SMEM 98304

__global__ void __launch_bounds__(256, 2)
k2_mma(const float* __restrict__ x, const float* __restrict__ w2,
       float* __restrict__ out)
{
    extern __shared__ char smem[];
    const int tid  = threadIdx.x;
    const int wid  = tid >> 5;
    const int lane = tid & 31;
    const float a2 = 0.17677669529663687f;  // 1/sqrt(32)

    for (int idx = tid; idx < 32 * 32; idx += 256) {
        int u = idx >> 5, w = idx & 31;
        float v = a2 * w2[idx];
        __nv_bfloat16 h, l;
        split_bf16(v, h, l);
        *(__nv_bfloat16*)(smem + K2_BH + (w * K2_ST + u) * 2) = h;
        *(__nv_bfloat16*)(smem + K2_BL + (w * K2_ST + u) * 2) = l;
    }

    const int mt = wid >> 1;
    const int nh = wid & 1;
    const int ar = mt * 16 + (lane >> 2);
    const int ak = (lane & 3) * 2;
    const int bn = lane >> 2;
    const int np = (lane & 3) * 2;
    float* st = (float*)(smem + K2_OUT);

    for (int t = blockIdx.x; t < NTILES; t += gridDim.x) {
        const int row0 = t * BM;
        __syncthreads();

        #pragma unroll
        for (int it = 0; it < 2; it++) {
            int i = tid + it * 256;
            int r = i >> 3, g = i & 7;
            const float* xp = x + (size_t)(row0 + r) * LDIM + 320 + g * 20;
            float f[20];
            #pragma unroll
            for (int q = 0; q < 5; q++)
                *(float4*)(f + 4 * q) = *(const float4*)(xp + 4 * q);
            #pragma unroll
            for (int ch = 0; ch < 5; ch++) {
                float g4[4] = {f[ch], f[ch + 5], f[ch + 10], f[ch + 15]};
                uint2 hi, lo;
                split4(g4, hi, lo);
                uint32_t o = (uint32_t)(ch * K2_ABLK) + (uint32_t)(r * K2_ST + 4 * g) * 2u;
                *(uint2*)(smem + K2_AH + o) = hi;
                *(uint2*)(smem + K2_AL + o) = lo;
            }
        }
        __syncthreads();

        const int rA = mt * 16 + (lane >> 2);
        #pragma unroll
        for (int ch = 0; ch < 5; ch++) {
            const uint32_t abase = (uint32_t)(ch * K2_ABLK) + (uint32_t)(ar * K2_ST + ak) * 2u;
            uint32_t ah[2][4], al[2][4];
            #pragma unroll
            for (int ks = 0; ks < 2; ks++) {
                uint32_t o = abase + (uint32_t)(ks * 16) * 2u;
                ah[ks][0] = *(const uint32_t*)(smem + K2_AH + o);
                ah[ks][1] = *(const uint32_t*)(smem + K2_AH + o + 8 * K2_ST * 2);
                ah[ks][2] = *(const uint32_t*)(smem + K2_AH + o + 16);
                ah[ks][3] = *(const uint32_t*)(smem + K2_AH + o + 8 * K2_ST * 2 + 16);
                al[ks][0] = *(const uint32_t*)(smem + K2_AL + o);
                al[ks][1] = *(const uint32_t*)(smem + K2_AL + o + 8 * K2_ST * 2);
                al[ks][2] = *(const uint32_t*)(smem + K2_AL + o + 16);
                al[ks][3] = *(const uint32_t*)(smem + K2_AL + o + 8 * K2_ST * 2 + 16);
            }
            #pragma unroll
            for (int q = 0; q < 2; q++) {
                const int nt = nh * 2 + q;
                float p0 = 0.f, p1 = 0.f, p2 = 0.f, p3 = 0.f;
                float q0 = 0.f, q1 = 0.f, q2 = 0.f, q3 = 0.f;
                float s0 = 0.f, s1 = 0.f, s2 = 0.f, s3 = 0.f;
                const uint32_t bbase = (uint32_t)((bn + nt * 8) * K2_ST + ak) * 2u;
                #pragma unroll
                for (int ks = 0; ks < 2; ks++) {
                    uint32_t o = bbase + (uint32_t)(ks * 16) * 2u;
                    uint32_t bh0 = *(const uint32_t*)(smem + K2_BH + o);
                    uint32_t bh1 = *(const uint32_t*)(smem + K2_BH + o + 16);
                    uint32_t bl0 = *(const uint32_t*)(smem + K2_BL + o);
                    uint32_t bl1 = *(const uint32_t*)(smem + K2_BL + o + 16);
                    mma_bf16(p0, p1, p2, p3, ah[ks][0], ah[ks][1], ah[ks][2], ah[ks][3], bh0, bh1);
                    mma_bf16(q0, q1, q2, q3, al[ks][0], al[ks][1], al[ks][2], al[ks][3], bh0, bh1);
                    mma_bf16(s0, s1, s2, s3, ah[ks][0], ah[ks][1], ah[ks][2], ah[ks][3], bl0, bl1);
                }
                const int n0 = nt * 8 + np;
                const int col = 5 * n0 + ch;
                st[rA * K2_OST + col]           = p0 + q0 + s0;
                st[rA * K2_OST + col + 5]       = p1 + q1 + s1;
                st[(rA + 8) * K2_OST + col]     = p2 + q2 + s2;
                st[(rA + 8) * K2_OST + col + 5] = p3 + q3 + s3;
            }
        }
        __syncthreads();

        #pragma unroll
        for (int it = 0; it < 10; it++) {
            int i = tid + it * 256;
            int r = i / 40, c4 = (i - r * 40) * 4;
            float4 v = *(const float4*)(st + r * K2_OST + c4);
            *(float4*)(out + (size_t)(row0 + r) * LDIM + 320 + c4) = v;
        }
    }
}

// ============================================================================

extern "C" void kernel_launch(void* const* d_in, const int* in_sizes, int n_in,
                              void* d_out, int out_size)
{
    const float* x  = (const float*)d_in[0];
    const float* w0 = (const float*)d_in[1];
    const float* w1 = (const float*)d_in[2];
    const float* w2 = (const float*)d_in[3];
    const float* b0 = (const float*)d_in[4];
    float* out = (float*)d_out;

    cudaFuncSetAttribute(k0_mma, cudaFuncAttributeMaxDynamicSharedMemorySize, K0_SMEM);
    cudaFuncSetAttribute(k1_mma, cudaFuncAttributeMaxDynamicSharedMemorySize, K1_SMEM);
    cudaFuncSetAttribute(k2_mma, cudaFuncAttributeMaxDynamicSharedMemorySize, K2_SMEM);

    k0_mma<<<304, 256, K0_SMEM>>>(x, w0, b0, out);
    k1_mma<<<304, 256, K1_SMEM>>>(x, w1, out);
    k2_mma<<<304, 256, K2_SMEM>>>(x, w2, out);
}

// round 9
// speedup vs baseline: 1.0075x; 1.0075x over previous
#include <cuda_runtime.h>
#include <cuda_bf16.h>
#include <cstdint>

#define NROWS 200000
#define NTILES 3125          // 200000 / 64
#define BM 64
#define LDIM 480

// ============================ HMMA helpers ============================
__device__ __forceinline__ void mma_bf16(float& c0, float& c1, float& c2, float& c3,
                                         uint32_t a0, uint32_t a1, uint32_t a2, uint32_t a3,
                                         uint32_t b0, uint32_t b1)
{
    asm volatile("mma.sync.aligned.m16n8k16.row.col.f32.bf16.bf16.f32 "
                 "{%0,%1,%2,%3}, {%4,%5,%6,%7}, {%8,%9}, {%0,%1,%2,%3};"
                 : "+f"(c0), "+f"(c1), "+f"(c2), "+f"(c3)
                 : "r"(a0), "r"(a1), "r"(a2), "r"(a3), "r"(b0), "r"(b1));
}

__device__ __forceinline__ uint32_t pack_hi(float x, float y, float& rx, float& ry) {
    __nv_bfloat162 h = __float22bfloat162_rn(make_float2(x, y));
    float2 hf = __bfloat1622float2(h);
    rx = x - hf.x; ry = y - hf.y;
    return *(uint32_t*)&h;
}
__device__ __forceinline__ uint32_t pack_lo(float rx, float ry) {
    __nv_bfloat162 l = __float22bfloat162_rn(make_float2(rx, ry));
    return *(uint32_t*)&l;
}
__device__ __forceinline__ void split_bf16(float v, __nv_bfloat16& h, __nv_bfloat16& l) {
    h = __float2bfloat16(v);
    l = __float2bfloat16(v - __bfloat162float(h));
}
__device__ __forceinline__ void split4(const float* f, uint2& hi, uint2& lo) {
    float r0, r1, r2, r3;
    uint32_t h0 = pack_hi(f[0], f[1], r0, r1);
    uint32_t h1 = pack_hi(f[2], f[3], r2, r3);
    hi = make_uint2(h0, h1);
    lo = make_uint2(pack_lo(r0, r1), pack_lo(r2, r3));
}

// ============================================================================
// Kernel 0 (HMMA, 32x32 warp tile): out[:, 0:128]
// 8 warps = 2 m-halves (32 rows) x 4 n-strips (32 cols).
// Each B fragment serves 2 m-subtiles from regs -> B crossbar traffic halved.
// smem: b0s[0,512) B_il[512,70144) ({hi,lo} uint2 per (n,kpair), row 68 uint2)
//       AH[70144,87552) AL[87552,104960) bf16 stride 136.
// ============================================================================
#define K0_STRIDE 136
#define K0_B0   0
#define K0_BIL  512
#define K0_BROW 68            // uint2 per B row
#define K0_AH   70144
#define K0_AL   87552
#define K0_SMEM 104960

__global__ void __launch_bounds__(256, 2)
k0_mma(const float* __restrict__ x, const float* __restrict__ w0,
       const float* __restrict__ b0, float* __restrict__ out)
{
    extern __shared__ char smem[];
    float* b0s = (float*)(smem + K0_B0);
    uint2* bil = (uint2*)(smem + K0_BIL);

    const int tid  = threadIdx.x;
    const int wid  = tid >> 5;
    const int lane = tid & 31;
    const float a0 = 0.08838834764831845f;   // 1/sqrt(128)

    // stage B interleaved: (n, kp) -> {hi(2kp,2kp+1), lo(2kp,2kp+1)}
    for (int idx = tid; idx < 128 * 64; idx += 256) {
        int n = idx & 127, kp = idx >> 7;
        float v0 = a0 * w0[(2 * kp) * 128 + n];
        float v1 = a0 * w0[(2 * kp + 1) * 128 + n];
        float r0, r1;
        uint32_t hi = pack_hi(v0, v1, r0, r1);
        uint32_t lo = pack_lo(r0, r1);
        bil[n * K0_BROW + kp] = make_uint2(hi, lo);
    }
    if (tid < 128) b0s[tid] = b0[tid];

    const int mh = wid >> 2;                 // m-half 0..1 (32 rows)
    const int ns = wid & 3;                  // n-strip 0..3 (32 cols)
    const int lq = lane >> 2;                // quad row 0..7
    const int kq = lane & 3;                 // k-pair lane
    const int ak = kq * 2;

    __syncthreads();

    for (int t = blockIdx.x; t < NTILES; t += gridDim.x) {
        const int row0 = t * BM;

        #pragma unroll
        for (int i = tid; i < 64 * 32; i += 256) {
            int r = i >> 5, c4 = (i & 31) << 2;
            float4 v = *(const float4*)(x + (size_t)(row0 + r) * LDIM + c4);
            float rx, ry, rz, rw;
            uint32_t h0 = pack_hi(v.x, v.y, rx, ry);
            uint32_t h1 = pack_hi(v.z, v.w, rz, rw);
            uint32_t l0 = pack_lo(rx, ry);
            uint32_t l1 = pack_lo(rz, rw);
            uint32_t off = (uint32_t)(r * K0_STRIDE + c4) * 2u;
            *(uint2*)(smem + K0_AH + off) = make_uint2(h0, h1);
            *(uint2*)(smem + K0_AL + off) = make_uint2(l0, l1);
        }
        __syncthreads();

        // C[mt][nt][4], bias-initialized
        float C[2][4][4];
        #pragma unroll
        for (int nt = 0; nt < 4; nt++) {
            float bias0 = b0s[ns * 32 + nt * 8 + ak];
            float bias1 = b0s[ns * 32 + nt * 8 + ak + 1];
            #pragma unroll
            for (int mt = 0; mt < 2; mt++) {
                C[mt][nt][0] = bias0; C[mt][nt][1] = bias1;
                C[mt][nt][2] = bias0; C[mt][nt][3] = bias1;
            }
        }

        #pragma unroll
        for (int ks = 0; ks < 8; ks++) {
            // A fragments for this ks: 2 m-subtiles x (4 hi + 4 lo)
            uint32_t ah[2][4], al[2][4];
            #pragma unroll
            for (int mt = 0; mt < 2; mt++) {
                const int ar = mh * 32 + mt * 16 + lq;
                uint32_t o = (uint32_t)(ar * K0_STRIDE + ak + ks * 16) * 2u;
                ah[mt][0] = *(const uint32_t*)(smem + K0_AH + o);
                ah[mt][1] = *(const uint32_t*)(smem + K0_AH + o + 8 * K0_STRIDE * 2);
                ah[mt][2] = *(const uint32_t*)(smem + K0_AH + o + 16);
                ah[mt][3] = *(const uint32_t*)(smem + K0_AH + o + 8 * K0_STRIDE * 2 + 16);
                al[mt][0] = *(const uint32_t*)(smem + K0_AL + o);
                al[mt][1] = *(const uint32_t*)(smem + K0_AL + o + 8 * K0_STRIDE * 2);
                al[mt][2] = *(const uint32_t*)(smem + K0_AL + o + 16);
                al[mt][3] = *(const uint32_t*)(smem + K0_AL + o + 8 * K0_STRIDE * 2 + 16);
            }

            const int kpb = ks * 8 + kq;
            #pragma unroll
            for (int nt = 0; nt < 4; nt++) {
                const uint2* brow = bil + (ns * 32 + nt * 8 + lq) * K0_BROW;
                uint2 bv0 = brow[kpb];        // {bh0, bl0}
                uint2 bv1 = brow[kpb + 4];    // {bh1, bl1}
                #pragma unroll
                for (int mt = 0; mt < 2; mt++) {
                    mma_bf16(C[mt][nt][0], C[mt][nt][1], C[mt][nt][2], C[mt][nt][3],
                             ah[mt][0], ah[mt][1], ah[mt][2], ah[mt][3], bv0.x, bv1.x);
                    mma_bf16(C[mt][nt][0], C[mt][nt][1], C[mt][nt][2], C[mt][nt][3],
                             al[mt][0], al[mt][1], al[mt][2], al[mt][3], bv0.x, bv1.x);
                    mma_bf16(C[mt][nt][0], C[mt][nt][1], C[mt][nt][2], C[mt][nt][3],
                             ah[mt][0], ah[mt][1], ah[mt][2], ah[mt][3], bv0.y, bv1.y);
                }
            }
        }

        #pragma unroll
        for (int mt = 0; mt < 2; mt++) {
            const int grow = row0 + mh * 32 + mt * 16 + lq;
            #pragma unroll
            for (int nt = 0; nt < 4; nt++) {
                float* o0 = out + (size_t)grow * LDIM + ns * 32 + nt * 8 + ak;
                *(float2*)o0              = make_float2(C[mt][nt][0], C[mt][nt][1]);
                *(float2*)(o0 + 8 * LDIM) = make_float2(C[mt][nt][2], C[mt][nt][3]);
            }
        }
        __syncthreads();
    }
}

// ============================================================================
// Kernel 1 (unchanged from R8 passing): out[:, 128+3w+i]
// ============================================================================
#define K1_ST 72
#define K1_BH 0
#define K1_BL 9216
#define K1_AH 18432
#define K1_AL 46080
#define K1_ABLK 9216
#define K1_OUT 18432          // overlay on Ah/Al
#define K1_OST 196
#define K1_SMEM 73728

__global__ void __launch_bounds__(256, 2)
k1_mma(const float* __restrict__ x, const float* __restrict__ w1,
       float* __restrict__ out)
{
    extern __shared__ char smem[];
    const int tid  = threadIdx.x;
    const int wid  = tid >> 5;
    const int lane = tid & 31;
    const float a1 = 0.125f;   // 1/sqrt(64)

    for (int idx = tid; idx < 64 * 64; idx += 256) {
        int u = idx >> 6, w = idx & 63;
        float v = a1 * w1[idx];
        __nv_bfloat16 h, l;
        split_bf16(v, h, l);
        *(__nv_bfloat16*)(smem + K1_BH + (w * K1_ST + u) * 2) = h;
        *(__nv_bfloat16*)(smem + K1_BL + (w * K1_ST + u) * 2) = l;
    }

    const int mt = wid >> 1;
    const int nh = wid & 1;
    const int ar = mt * 16 + (lane >> 2);
    const int ak = (lane & 3) * 2;
    const int bn = lane >> 2;
    const int np = (lane & 3) * 2;

    for (int t = blockIdx.x; t < NTILES; t += gridDim.x) {
        const int row0 = t * BM;
        __syncthreads();

        #pragma unroll
        for (int it = 0; it < 4; it++) {
            int i = tid + it * 256;
            int r = i >> 4, g = i & 15;
            const float* xp = x + (size_t)(row0 + r) * LDIM + 128 + g * 12;
            float f[12];
            *(float4*)(f)     = *(const float4*)(xp);
            *(float4*)(f + 4) = *(const float4*)(xp + 4);
            *(float4*)(f + 8) = *(const float4*)(xp + 8);
            #pragma unroll
            for (int ch = 0; ch < 3; ch++) {
                float g4[4] = {f[ch], f[ch + 3], f[ch + 6], f[ch + 9]};
                uint2 hi, lo;
                split4(g4, hi, lo);
                uint32_t o = (uint32_t)(ch * K1_ABLK) + (uint32_t)(r * K1_ST + 4 * g) * 2u;
                *(uint2*)(smem + K1_AH + o) = hi;
                *(uint2*)(smem + K1_AL + o) = lo;
            }
        }
        __syncthreads();

        float C[3][4][4];
        #pragma unroll
        for (int ch = 0; ch < 3; ch++) {
            const uint32_t abase = (uint32_t)(ch * K1_ABLK) + (uint32_t)(ar * K1_ST + ak) * 2u;
            uint32_t ah[4][4], al[4][4];
            #pragma unroll
            for (int ks = 0; ks < 4; ks++) {
                uint32_t o = abase + (uint32_t)(ks * 16) * 2u;
                ah[ks][0] = *(const uint32_t*)(smem + K1_AH + o);
                ah[ks][1] = *(const uint32_t*)(smem + K1_AH + o + 8 * K1_ST * 2);
                ah[ks][2] = *(const uint32_t*)(smem + K1_AH + o + 16);
                ah[ks][3] = *(const uint32_t*)(smem + K1_AH + o + 8 * K1_ST * 2 + 16);
                al[ks][0] = *(const uint32_t*)(smem + K1_AL + o);
                al[ks][1] = *(const uint32_t*)(smem + K1_AL + o + 8 * K1_ST * 2);
                al[ks][2] = *(const uint32_t*)(smem + K1_AL + o + 16);
                al[ks][3] = *(const uint32_t*)(smem + K1_AL + o + 8 * K1_ST * 2 + 16);
            }
            #pragma unroll
            for (int q = 0; q < 4; q++) {
                const int nt = nh * 4 + q;
                float p0 = 0.f, p1 = 0.f, p2 = 0.f, p3 = 0.f;
                float q0 = 0.f, q1 = 0.f, q2 = 0.f, q3 = 0.f;
                float s0 = 0.f, s1 = 0.f, s2 = 0.f, s3 = 0.f;
                const uint32_t bbase = (uint32_t)((bn + nt * 8) * K1_ST + ak) * 2u;
                #pragma unroll
                for (int ks = 0; ks < 4; ks++) {
                    uint32_t o = bbase + (uint32_t)(ks * 16) * 2u;
                    uint32_t bh0 = *(const uint32_t*)(smem + K1_BH + o);
                    uint32_t bh1 = *(const uint32_t*)(smem + K1_BH + o + 16);
                    uint32_t bl0 = *(const uint32_t*)(smem + K1_BL + o);
                    uint32_t bl1 = *(const uint32_t*)(smem + K1_BL + o + 16);
                    mma_bf16(p0, p1, p2, p3, ah[ks][0], ah[ks][1], ah[ks][2], ah[ks][3], bh0, bh1);
                    mma_bf16(q0, q1, q2, q3, al[ks][0], al[ks][1], al[ks][2], al[ks][3], bh0, bh1);
                    mma_bf16(s0, s1, s2, s3, ah[ks][0], ah[ks][1], ah[ks][2], ah[ks][3], bl0, bl1);
                }
                C[ch][q][0] = p0 + q0 + s0;
                C[ch][q][1] = p1 + q1 + s1;
                C[ch][q][2] = p2 + q2 + s2;
                C[ch][q][3] = p3 + q3 + s3;
            }
        }
        __syncthreads();

        {
            float* st = (float*)(smem + K1_OUT);
            const int rA = mt * 16 + (lane >> 2);
            #pragma unroll
            for (int ch = 0; ch < 3; ch++) {
                #pragma unroll
                for (int q = 0; q < 4; q++) {
                    const int n0 = (nh * 4 + q) * 8 + np;
                    const int col = 3 * n0 + ch;
                    st[rA * K1_OST + col]           = C[ch][q][0];
                    st[rA * K1_OST + col + 3]       = C[ch][q][1];
                    st[(rA + 8) * K1_OST + col]     = C[ch][q][2];
                    st[(rA + 8) * K1_OST + col + 3] = C[ch][q][3];
                }
            }
        }
        __syncthreads();

        {
            const float* st = (const float*)(smem + K1_OUT);
            #pragma unroll
            for (int it = 0; it < 12; it++) {
                int i = tid + it * 256;
                int r = i / 48, c4 = (i - r * 48) * 4;
                float4 v = *(const float4*)(st + r * K1_OST + c4);
                *(float4*)(out + (size_t)(row0 + r) * LDIM + 128 + c4) = v;
            }
        }
    }
}

// ============================================================================
// Kernel 2 (unchanged from R8 passing): out[:, 320+5w+i]
// ============================================================================
#define K2_ST 40
#define K2_BH 0
#define K2_BL 2560
#define K2_AH 5120
#define K2_AL 30720
#define K2_ABLK 5120
#define K2_OUT 56320
#define K2_OST 164
#define K2_SMEM 98304

__global__ void __launch_bounds__(256, 2)
k2_mma(const float* __restrict__ x, const float* __restrict__ w2,
       float* __restrict__ out)
{
    extern __shared__ char smem[];
    const int tid  = threadIdx.x;
    const int wid  = tid >> 5;
    const int lane = tid & 31;
    const float a2 = 0.17677669529663687f;  // 1/sqrt(32)

    for (int idx = tid; idx < 32 * 32; idx += 256) {
        int u = idx >> 5, w = idx & 31;
        float v = a2 * w2[idx];
        __nv_bfloat16 h, l;
        split_bf16(v, h, l);
        *(__nv_bfloat16*)(smem + K2_BH + (w * K2_ST + u) * 2) = h;
        *(__nv_bfloat16*)(smem + K2_BL + (w * K2_ST + u) * 2) = l;
    }

    const int mt = wid >> 1;
    const int nh = wid & 1;
    const int ar = mt * 16 + (lane >> 2);
    const int ak = (lane & 3) * 2;
    const int bn = lane >> 2;
    const int np = (lane & 3) * 2;
    float* st = (float*)(smem + K2_OUT);

    for (int t = blockIdx.x; t < NTILES; t += gridDim.x) {
        const int row0 = t * BM;
        __syncthreads();

        #pragma unroll
        for (int it = 0; it < 2; it++) {
            int i = tid + it * 256;
            int r = i >> 3, g = i & 7;
            const float* xp = x + (size_t)(row0 + r) * LDIM + 320 + g * 20;
            float f[20];
            #pragma unroll
            for (int q = 0; q < 5; q++)
                *(float4*)(f + 4 * q) = *(const float4*)(xp + 4 * q);
            #pragma unroll
            for (int ch = 0; ch < 5; ch++) {
                float g4[4] = {f[ch], f[ch + 5], f[ch + 10], f[ch + 15]};
                uint2 hi, lo;
                split4(g4, hi, lo);
                uint32_t o = (uint32_t)(ch * K2_ABLK) + (uint32_t)(r * K2_ST + 4 * g) * 2u;
                *(uint2*)(smem + K2_AH + o) = hi;
                *(uint2*)(smem + K2_AL + o) = lo;
            }
        }
        __syncthreads();

        const int rA = mt * 16 + (lane >> 2);
        #pragma unroll
        for (int ch = 0; ch < 5; ch++) {
            const uint32_t abase = (uint32_t)(ch * K2_ABLK) + (uint32_t)(ar * K2_ST + ak) * 2u;
            uint32_t ah[2][4], al[2][4];
            #pragma unroll
            for (int ks = 0; ks < 2; ks++) {
                uint32_t o = abase + (uint32_t)(ks * 16) * 2u;
                ah[ks][0] = *(const uint32_t*)(smem + K2_AH + o);
                ah[ks][1] = *(const uint32_t*)(smem + K2_AH + o + 8 * K2_ST * 2);
                ah[ks][2] = *(const uint32_t*)(smem + K2_AH + o + 16);
                ah[ks][3] = *(const uint32_t*)(smem + K2_AH + o + 8 * K2_ST * 2 + 16);
                al[ks][0] = *(const uint32_t*)(smem + K2_AL + o);
                al[ks][1] = *(const uint32_t*)(smem + K2_AL + o + 8 * K2_ST * 2);
                al[ks][2] = *(const uint32_t*)(smem + K2_AL + o + 16);
                al[ks][3] = *(const uint32_t*)(smem + K2_AL + o + 8 * K2_ST * 2 + 16);
            }
            #pragma unroll
            for (int q = 0; q < 2; q++) {
                const int nt = nh * 2 + q;
                float p0 = 0.f, p1 = 0.f, p2 = 0.f, p3 = 0.f;
                float q0 = 0.f, q1 = 0.f, q2 = 0.f, q3 = 0.f;
                float s0 = 0.f, s1 = 0.f, s2 = 0.f, s3 = 0.f;
                const uint32_t bbase = (uint32_t)((bn + nt * 8) * K2_ST + ak) * 2u;
                #pragma unroll
                for (int ks = 0; ks < 2; ks++) {
                    uint32_t o = bbase + (uint32_t)(ks * 16) * 2u;
                    uint32_t bh0 = *(const uint32_t*)(smem + K2_BH + o);
                    uint32_t bh1 = *(const uint32_t*)(smem + K2_BH + o + 16);
                    uint32_t bl0 = *(const uint32_t*)(smem + K2_BL + o);
                    uint32_t bl1 = *(const uint32_t*)(smem + K2_BL + o + 16);
                    mma_bf16(p0, p1, p2, p3, ah[ks][0], ah[ks][1], ah[ks][2], ah[ks][3], bh0, bh1);
                    mma_bf16(q0, q1, q2, q3, al[ks][0], al[ks][1], al[ks][2], al[ks][3], bh0, bh1);
                    mma_bf16(s0, s1, s2, s3, ah[ks][0], ah[ks][1], ah[ks][2], ah[ks][3], bl0, bl1);
                }
                const int n0 = nt * 8 + np;
                const int col = 5 * n0 + ch;
                st[rA * K2_OST + col]           = p0 + q0 + s0;
                st[rA * K2_OST + col + 5]       = p1 + q1 + s1;
                st[(rA + 8) * K2_OST + col]     = p2 + q2 + s2;
                st[(rA + 8) * K2_OST + col + 5] = p3 + q3 + s3;
            }
        }
        __syncthreads();

        #pragma unroll
        for (int it = 0; it < 10; it++) {
            int i = tid + it * 256;
            int r = i / 40, c4 = (i - r * 40) * 4;
            float4 v = *(const float4*)(st + r * K2_OST + c4);
            *(float4*)(out + (size_t)(row0 + r) * LDIM + 320 + c4) = v;
        }
    }
}

// ============================================================================

extern "C" void kernel_launch(void* const* d_in, const int* in_sizes, int n_in,
                              void* d_out, int out_size)
{
    const float* x  = (const float*)d_in[0];
    const float* w0 = (const float*)d_in[1];
    const float* w1 = (const float*)d_in[2];
    const float* w2 = (const float*)d_in[3];
    const float* b0 = (const float*)d_in[4];
    float* out = (float*)d_out;

    cudaFuncSetAttribute(k0_mma, cudaFuncAttributeMaxDynamicSharedMemorySize, K0_SMEM);
    cudaFuncSetAttribute(k1_mma, cudaFuncAttributeMaxDynamicSharedMemorySize, K1_SMEM);
    cudaFuncSetAttribute(k2_mma, cudaFuncAttributeMaxDynamicSharedMemorySize, K2_SMEM);

    k0_mma<<<304, 256, K0_SMEM>>>(x, w0, b0, out);
    k1_mma<<<304, 256, K1_SMEM>>>(x, w1, out);
    k2_mma<<<304, 256, K2_SMEM>>>(x, w2, out);
}

// round 10
// speedup vs baseline: 1.0241x; 1.0164x over previous
#include <cuda_runtime.h>
#include <cuda_bf16.h>
#include <cstdint>

#define NROWS 200000
#define NTILES 3125          // 200000 / 64 (k1/k2)
#define BM 64
#define LDIM 480

// ============================ HMMA helpers ============================
__device__ __forceinline__ void mma_bf16(float& c0, float& c1, float& c2, float& c3,
                                         uint32_t a0, uint32_t a1, uint32_t a2, uint32_t a3,
                                         uint32_t b0, uint32_t b1)
{
    asm volatile("mma.sync.aligned.m16n8k16.row.col.f32.bf16.bf16.f32 "
                 "{%0,%1,%2,%3}, {%4,%5,%6,%7}, {%8,%9}, {%0,%1,%2,%3};"
                 : "+f"(c0), "+f"(c1), "+f"(c2), "+f"(c3)
                 : "r"(a0), "r"(a1), "r"(a2), "r"(a3), "r"(b0), "r"(b1));
}

__device__ __forceinline__ uint32_t pack_hi(float x, float y, float& rx, float& ry) {
    __nv_bfloat162 h = __float22bfloat162_rn(make_float2(x, y));
    float2 hf = __bfloat1622float2(h);
    rx = x - hf.x; ry = y - hf.y;
    return *(uint32_t*)&h;
}
__device__ __forceinline__ uint32_t pack_lo(float rx, float ry) {
    __nv_bfloat162 l = __float22bfloat162_rn(make_float2(rx, ry));
    return *(uint32_t*)&l;
}
__device__ __forceinline__ void split_bf16(float v, __nv_bfloat16& h, __nv_bfloat16& l) {
    h = __float2bfloat16(v);
    l = __float2bfloat16(v - __bfloat162float(h));
}
__device__ __forceinline__ void split4(const float* f, uint2& hi, uint2& lo) {
    float r0, r1, r2, r3;
    uint32_t h0 = pack_hi(f[0], f[1], r0, r1);
    uint32_t h1 = pack_hi(f[2], f[3], r2, r3);
    hi = make_uint2(h0, h1);
    lo = make_uint2(pack_lo(r0, r1), pack_lo(r2, r3));
}

__device__ __forceinline__ void cp_async16(uint32_t dst, const void* src, bool pred) {
    int sz = pred ? 16 : 0;
    asm volatile("cp.async.cg.shared.global [%0], [%1], 16, %2;"
                 :: "r"(dst), "l"(src), "r"(sz) : "memory");
}
#define CP_COMMIT()  asm volatile("cp.async.commit_group;" ::: "memory")
#define CP_WAIT(n)   asm volatile("cp.async.wait_group %0;" :: "n"(n) : "memory")

// ============================================================================
// Kernel 0 (HMMA, cp.async double-buffered pipeline): out[:, 0:128]
// 1 CTA/SM, 512 threads, BM=128. 16 warps = 4 m-halves x 4 n-strips (32x32).
// A staged as fp32 via cp.async (double buffer); bf16 hi/lo conversion happens
// during fragment load. B interleaved {hi,lo} per (n, kpair).
// smem: b0s[0,512) B_il[512,70144) A0[70144,139776) A1[139776,209408)
// ============================================================================
#define T0_TILES 1563         // ceil(200000/128)
#define BM0 128
#define K0_AST 136            // fp32 A row stride (floats)
#define K0_B0   0
#define K0_BIL  512
#define K0_BROW 68            // uint2 per B row
#define K0_A0   70144
#define K0_A1   139776
#define K0_SMEM 209408

__global__ void __launch_bounds__(512, 1)
k0_mma(const float* __restrict__ x, const float* __restrict__ w0,
       const float* __restrict__ b0, float* __restrict__ out)
{
    extern __shared__ char smem[];
    float* b0s = (float*)(smem + K0_B0);
    uint2* bil = (uint2*)(smem + K0_BIL);

    const int tid  = threadIdx.x;
    const int wid  = tid >> 5;
    const int lane = tid & 31;
    const float a0 = 0.08838834764831845f;   // 1/sqrt(128)

    // stage B interleaved: (n, kp) -> {hi(2kp,2kp+1), lo(2kp,2kp+1)}
    for (int idx = tid; idx < 128 * 64; idx += 512) {
        int n = idx & 127, kp = idx >> 7;
        float v0 = a0 * w0[(2 * kp) * 128 + n];
        float v1 = a0 * w0[(2 * kp + 1) * 128 + n];
        float r0, r1;
        uint32_t hi = pack_hi(v0, v1, r0, r1);
        uint32_t lo = pack_lo(r0, r1);
        bil[n * K0_BROW + kp] = make_uint2(hi, lo);
    }
    if (tid < 128) b0s[tid] = b0[tid];
    __syncthreads();

    const int mh = wid >> 2;                 // m-half 0..3 (32 rows each)
    const int ns = wid & 3;                  // n-strip 0..3 (32 cols each)
    const int lq = lane >> 2;                // quad row 0..7
    const int kq = lane & 3;                 // k-pair lane
    const int ak = kq * 2;

    const uint32_t abase0 = (uint32_t)__cvta_generic_to_shared(smem + K0_A0);
    const uint32_t abase1 = (uint32_t)__cvta_generic_to_shared(smem + K0_A1);

    // ---- prologue: issue first tile into buf0 ----
    int t = blockIdx.x;
    if (t < T0_TILES) {
        const int row0 = t * BM0;
        #pragma unroll
        for (int it = 0; it < 8; it++) {
            int i = tid + it * 512;
            int r = i >> 5, c4 = (i & 31) << 2;
            int grow = row0 + r;
            bool p = grow < NROWS;
            const float* src = x + (size_t)(p ? grow : 0) * LDIM + c4;
            cp_async16(abase0 + (uint32_t)(r * K0_AST + c4) * 4u, src, p);
        }
        CP_COMMIT();
    }

    int cur = 0;
    for (; t < T0_TILES; t += gridDim.x) {
        const int row0 = t * BM0;
        const int tn = t + gridDim.x;

        // issue next tile into the other buffer, then wait for current
        if (tn < T0_TILES) {
            const int nrow0 = tn * BM0;
            const uint32_t nb = cur ? abase0 : abase1;
            #pragma unroll
            for (int it = 0; it < 8; it++) {
                int i = tid + it * 512;
                int r = i >> 5, c4 = (i & 31) << 2;
                int grow = nrow0 + r;
                bool p = grow < NROWS;
                const float* src = x + (size_t)(p ? grow : 0) * LDIM + c4;
                cp_async16(nb + (uint32_t)(r * K0_AST + c4) * 4u, src, p);
            }
            CP_COMMIT();
            CP_WAIT(1);
        } else {
            CP_WAIT(0);
        }
        __syncthreads();

        const float* A = (const float*)(smem + (cur ? K0_A1 : K0_A0));

        // C[mt][nt][4], bias-initialized
        float C[2][4][4];
        #pragma unroll
        for (int nt = 0; nt < 4; nt++) {
            float bias0 = b0s[ns * 32 + nt * 8 + ak];
            float bias1 = b0s[ns * 32 + nt * 8 + ak + 1];
            #pragma unroll
            for (int mt = 0; mt < 2; mt++) {
                C[mt][nt][0] = bias0; C[mt][nt][1] = bias1;
                C[mt][nt][2] = bias0; C[mt][nt][3] = bias1;
            }
        }

        #pragma unroll
        for (int ks = 0; ks < 8; ks++) {
            // load fp32 A fragments, convert to bf16 hi/lo in regs
            uint32_t ah[2][4], al[2][4];
            #pragma unroll
            for (int mt = 0; mt < 2; mt++) {
                const int ar = mh * 32 + mt * 16 + lq;
                const float* ap = A + ar * K0_AST + ak + ks * 16;
                float2 f0 = *(const float2*)(ap);
                float2 f1 = *(const float2*)(ap + 8 * K0_AST);
                float2 f2 = *(const float2*)(ap + 8);
                float2 f3 = *(const float2*)(ap + 8 * K0_AST + 8);
                float rx, ry;
                ah[mt][0] = pack_hi(f0.x, f0.y, rx, ry); al[mt][0] = pack_lo(rx, ry);
                ah[mt][1] = pack_hi(f1.x, f1.y, rx, ry); al[mt][1] = pack_lo(rx, ry);
                ah[mt][2] = pack_hi(f2.x, f2.y, rx, ry); al[mt][2] = pack_lo(rx, ry);
                ah[mt][3] = pack_hi(f3.x, f3.y, rx, ry); al[mt][3] = pack_lo(rx, ry);
            }

            const int kpb = ks * 8 + kq;
            #pragma unroll
            for (int nt = 0; nt < 4; nt++) {
                const uint2* brow = bil + (ns * 32 + nt * 8 + lq) * K0_BROW;
                uint2 bv0 = brow[kpb];        // {bh0, bl0}
                uint2 bv1 = brow[kpb + 4];    // {bh1, bl1}
                #pragma unroll
                for (int mt = 0; mt < 2; mt++) {
                    mma_bf16(C[mt][nt][0], C[mt][nt][1], C[mt][nt][2], C[mt][nt][3],
                             ah[mt][0], ah[mt][1], ah[mt][2], ah[mt][3], bv0.x, bv1.x);
                    mma_bf16(C[mt][nt][0], C[mt][nt][1], C[mt][nt][2], C[mt][nt][3],
                             al[mt][0], al[mt][1], al[mt][2], al[mt][3], bv0.x, bv1.x);
                    mma_bf16(C[mt][nt][0], C[mt][nt][1], C[mt][nt][2], C[mt][nt][3],
                             ah[mt][0], ah[mt][1], ah[mt][2], ah[mt][3], bv0.y, bv1.y);
                }
            }
        }

        // epilogue (guarded for tail tile)
        #pragma unroll
        for (int mt = 0; mt < 2; mt++) {
            const int grow = row0 + mh * 32 + mt * 16 + lq;
            #pragma unroll
            for (int nt = 0; nt < 4; nt++) {
                float* o0 = out + (size_t)grow * LDIM + ns * 32 + nt * 8 + ak;
                if (grow < NROWS)
                    *(float2*)o0 = make_float2(C[mt][nt][0], C[mt][nt][1]);
                if (grow + 8 < NROWS)
                    *(float2*)(o0 + 8 * LDIM) = make_float2(C[mt][nt][2], C[mt][nt][3]);
            }
        }
        __syncthreads();   // all reads of buf[cur] done before next issue overwrites it
        cur ^= 1;
    }
}

// ============================================================================
// Kernel 1 (unchanged from R9 passing): out[:, 128+3w+i]
// ============================================================================
#define K1_ST 72
#define K1_BH 0
#define K1_BL 9216
#define K1_AH 18432
#define K1_AL 46080
#define K1_ABLK 9216
#define K1_OUT 18432          // overlay on Ah/Al
#define K1_OST 196
#define K1_SMEM 73728

__global__ void __launch_bounds__(256, 2)
k1_mma(const float* __restrict__ x, const float* __restrict__ w1,
       float* __restrict__ out)
{
    extern __shared__ char smem[];
    const int tid  = threadIdx.x;
    const int wid  = tid >> 5;
    const int lane = tid & 31;
    const float a1 = 0.125f;   // 1/sqrt(64)

    for (int idx = tid; idx < 64 * 64; idx += 256) {
        int u = idx >> 6, w = idx & 63;
        float v = a1 * w1[idx];
        __nv_bfloat16 h, l;
        split_bf16(v, h, l);
        *(__nv_bfloat16*)(smem + K1_BH + (w * K1_ST + u) * 2) = h;
        *(__nv_bfloat16*)(smem + K1_BL + (w * K1_ST + u) * 2) = l;
    }

    const int mt = wid >> 1;
    const int nh = wid & 1;
    const int ar = mt * 16 + (lane >> 2);
    const int ak = (lane & 3) * 2;
    const int bn = lane >> 2;
    const int np = (lane & 3) * 2;

    for (int t = blockIdx.x; t < NTILES; t += gridDim.x) {
        const int row0 = t * BM;
        __syncthreads();

        #pragma unroll
        for (int it = 0; it < 4; it++) {
            int i = tid + it * 256;
            int r = i >> 4, g = i & 15;
            const float* xp = x + (size_t)(row0 + r) * LDIM + 128 + g * 12;
            float f[12];
            *(float4*)(f)     = *(const float4*)(xp);
            *(float4*)(f + 4) = *(const float4*)(xp + 4);
            *(float4*)(f + 8) = *(const float4*)(xp + 8);
            #pragma unroll
            for (int ch = 0; ch < 3; ch++) {
                float g4[4] = {f[ch], f[ch + 3], f[ch + 6], f[ch + 9]};
                uint2 hi, lo;
                split4(g4, hi, lo);
                uint32_t o = (uint32_t)(ch * K1_ABLK) + (uint32_t)(r * K1_ST + 4 * g) * 2u;
                *(uint2*)(smem + K1_AH + o) = hi;
                *(uint2*)(smem + K1_AL + o) = lo;
            }
        }
        __syncthreads();

        float C[3][4][4];
        #pragma unroll
        for (int ch = 0; ch < 3; ch++) {
            const uint32_t abase = (uint32_t)(ch * K1_ABLK) + (uint32_t)(ar * K1_ST + ak) * 2u;
            uint32_t ah[4][4], al[4][4];
            #pragma unroll
            for (int ks = 0; ks < 4; ks++) {
                uint32_t o = abase + (uint32_t)(ks * 16) * 2u;
                ah[ks][0] = *(const uint32_t*)(smem + K1_AH + o);
                ah[ks][1] = *(const uint32_t*)(smem + K1_AH + o + 8 * K1_ST * 2);
                ah[ks][2] = *(const uint32_t*)(smem + K1_AH + o + 16);
                ah[ks][3] = *(const uint32_t*)(smem + K1_AH + o + 8 * K1_ST * 2 + 16);
                al[ks][0] = *(const uint32_t*)(smem + K1_AL + o);
                al[ks][1] = *(const uint32_t*)(smem + K1_AL + o + 8 * K1_ST * 2);
                al[ks][2] = *(const uint32_t*)(smem + K1_AL + o + 16);
                al[ks][3] = *(const uint32_t*)(smem + K1_AL + o + 8 * K1_ST * 2 + 16);
            }
            #pragma unroll
            for (int q = 0; q < 4; q++) {
                const int nt = nh * 4 + q;
                float p0 = 0.f, p1 = 0.f, p2 = 0.f, p3 = 0.f;
                float q0 = 0.f, q1 = 0.f, q2 = 0.f, q3 = 0.f;
                float s0 = 0.f, s1 = 0.f, s2 = 0.f, s3 = 0.f;
                const uint32_t bbase = (uint32_t)((bn + nt * 8) * K1_ST + ak) * 2u;
                #pragma unroll
                for (int ks = 0; ks < 4; ks++) {
                    uint32_t o = bbase + (uint32_t)(ks * 16) * 2u;
                    uint32_t bh0 = *(const uint32_t*)(smem + K1_BH + o);
                    uint32_t bh1 = *(const uint32_t*)(smem + K1_BH + o + 16);
                    uint32_t bl0 = *(const uint32_t*)(smem + K1_BL + o);
                    uint32_t bl1 = *(const uint32_t*)(smem + K1_BL + o + 16);
                    mma_bf16(p0, p1, p2, p3, ah[ks][0], ah[ks][1], ah[ks][2], ah[ks][3], bh0, bh1);
                    mma_bf16(q0, q1, q2, q3, al[ks][0], al[ks][1], al[ks][2], al[ks][3], bh0, bh1);
                    mma_bf16(s0, s1, s2, s3, ah[ks][0], ah[ks][1], ah[ks][2], ah[ks][3], bl0, bl1);
                }
                C[ch][q][0] = p0 + q0 + s0;
                C[ch][q][1] = p1 + q1 + s1;
                C[ch][q][2] = p2 + q2 + s2;
                C[ch][q][3] = p3 + q3 + s3;
            }
        }
        __syncthreads();

        {
            float* st = (float*)(smem + K1_OUT);
            const int rA = mt * 16 + (lane >> 2);
            #pragma unroll
            for (int ch = 0; ch < 3; ch++) {
                #pragma unroll
                for (int q = 0; q < 4; q++) {
                    const int n0 = (nh * 4 + q) * 8 + np;
                    const int col = 3 * n0 + ch;
                    st[rA * K1_OST + col]           = C[ch][q][0];
                    st[rA * K1_OST + col + 3]       = C[ch][q][1];
                    st[(rA + 8) * K1_OST + col]     = C[ch][q][2];
                    st[(rA + 8) * K1_OST + col + 3] = C[ch][q][3];
                }
            }
        }
        __syncthreads();

        {
            const float* st = (const float*)(smem + K1_OUT);
            #pragma unroll
            for (int it = 0; it < 12; it++) {
                int i = tid + it * 256;
                int r = i / 48, c4 = (i - r * 48) * 4;
                float4 v = *(const float4*)(st + r * K1_OST + c4);
                *(float4*)(out + (size_t)(row0 + r) * LDIM + 128 + c4) = v;
            }
        }
    }
}

// ============================================================================
// Kernel 2 (unchanged from R9 passing): out[:, 320+5w+i]
// ============================================================================
#define K2_ST 40
#define K2_BH 0
#define K2_BL 2560
#define K2_AH 5120
#define K2_AL 30720
#define K2_ABLK 5120
#define K2_OUT 56320
#define K2_OST 164
#define K2_SMEM 98304

__global__ void __launch_bounds__(256, 2)
k2_mma(const float* __restrict__ x, const float* __restrict__ w2,
       float* __restrict__ out)
{
    extern __shared__ char smem[];
    const int tid  = threadIdx.x;
    const int wid  = tid >> 5;
    const int lane = tid & 31;
    const float a2 = 0.17677669529663687f;  // 1/sqrt(32)

    for (int idx = tid; idx < 32 * 32; idx += 256) {
        int u = idx >> 5, w = idx & 31;
        float v = a2 * w2[idx];
        __nv_bfloat16 h, l;
        split_bf16(v, h, l);
        *(__nv_bfloat16*)(smem + K2_BH + (w * K2_ST + u) * 2) = h;
        *(__nv_bfloat16*)(smem + K2_BL + (w * K2_ST + u) * 2) = l;
    }

    const int mt = wid >> 1;
    const int nh = wid & 1;
    const int ar = mt * 16 + (lane >> 2);
    const int ak = (lane & 3) * 2;
    const int bn = lane >> 2;
    const int np = (lane & 3) * 2;
    float* st = (float*)(smem + K2_OUT);

    for (int t = blockIdx.x; t < NTILES; t += gridDim.x) {
        const int row0 = t * BM;
        __syncthreads();

        #pragma unroll
        for (int it = 0; it < 2; it++) {
            int i = tid + it * 256;
            int r = i >> 3, g = i & 7;
            const float* xp = x + (size_t)(row0 + r) * LDIM + 320 + g * 20;
            float f[20];
            #pragma unroll
            for (int q = 0; q < 5; q++)
                *(float4*)(f + 4 * q) = *(const float4*)(xp + 4 * q);
            #pragma unroll
            for (int ch = 0; ch < 5; ch++) {
                float g4[4] = {f[ch], f[ch + 5], f[ch + 10], f[ch + 15]};
                uint2 hi, lo;
                split4(g4, hi, lo);
                uint32_t o = (uint32_t)(ch * K2_ABLK) + (uint32_t)(r * K2_ST + 4 * g) * 2u;
                *(uint2*)(smem + K2_AH + o) = hi;
                *(uint2*)(smem + K2_AL + o) = lo;
            }
        }
        __syncthreads();

        const int rA = mt * 16 + (lane >> 2);
        #pragma unroll
        for (int ch = 0; ch < 5; ch++) {
            const uint32_t abase = (uint32_t)(ch * K2_ABLK) + (uint32_t)(ar * K2_ST + ak) * 2u;
            uint32_t ah[2][4], al[2][4];
            #pragma unroll
            for (int ks = 0; ks < 2; ks++) {
                uint32_t o = abase + (uint32_t)(ks * 16) * 2u;
                ah[ks][0] = *(const uint32_t*)(smem + K2_AH + o);
                ah[ks][1] = *(const uint32_t*)(smem + K2_AH + o + 8 * K2_ST * 2);
                ah[ks][2] = *(const uint32_t*)(smem + K2_AH + o + 16);
                ah[ks][3] = *(const uint32_t*)(smem + K2_AH + o + 8 * K2_ST * 2 + 16);
                al[ks][0] = *(const uint32_t*)(smem + K2_AL + o);
                al[ks][1] = *(const uint32_t*)(smem + K2_AL + o + 8 * K2_ST * 2);
                al[ks][2] = *(const uint32_t*)(smem + K2_AL + o + 16);
                al[ks][3] = *(const uint32_t*)(smem + K2_AL + o + 8 * K2_ST * 2 + 16);
            }
            #pragma unroll
            for (int q = 0; q < 2; q++) {
                const int nt = nh * 2 + q;
                float p0 = 0.f, p1 = 0.f, p2 = 0.f, p3 = 0.f;
                float q0 = 0.f, q1 = 0.f, q2 = 0.f, q3 = 0.f;
                float s0 = 0.f, s1 = 0.f, s2 = 0.f, s3 = 0.f;
                const uint32_t bbase = (uint32_t)((bn + nt * 8) * K2_ST + ak) * 2u;
                #pragma unroll
                for (int ks = 0; ks < 2; ks++) {
                    uint32_t o = bbase + (uint32_t)(ks * 16) * 2u;
                    uint32_t bh0 = *(const uint32_t*)(smem + K2_BH + o);
                    uint32_t bh1 = *(const uint32_t*)(smem + K2_BH + o + 16);
                    uint32_t bl0 = *(const uint32_t*)(smem + K2_BL + o);
                    uint32_t bl1 = *(const uint32_t*)(smem + K2_BL + o + 16);
                    mma_bf16(p0, p1, p2, p3, ah[ks][0], ah[ks][1], ah[ks][2], ah[ks][3], bh0, bh1);
                    mma_bf16(q0, q1, q2, q3, al[ks][0], al[ks][1], al[ks][2], al[ks][3], bh0, bh1);
                    mma_bf16(s0, s1, s2, s3, ah[ks][0], ah[ks][1], ah[ks][2], ah[ks][3], bl0, bl1);
                }
                const int n0 = nt * 8 + np;
                const int col = 5 * n0 + ch;
                st[rA * K2_OST + col]           = p0 + q0 + s0;
                st[rA * K2_OST + col + 5]       = p1 + q1 + s1;
                st[(rA + 8) * K2_OST + col]     = p2 + q2 + s2;
                st[(rA + 8) * K2_OST + col + 5] = p3 + q3 + s3;
            }
        }
        __syncthreads();

        #pragma unroll
        for (int it = 0; it < 10; it++) {
            int i = tid + it * 256;
            int r = i / 40, c4 = (i - r * 40) * 4;
            float4 v = *(const float4*)(st + r * K2_OST + c4);
            *(float4*)(out + (size_t)(row0 + r) * LDIM + 320 + c4) = v;
        }
    }
}

// ============================================================================

extern "C" void kernel_launch(void* const* d_in, const int* in_sizes, int n_in,
                              void* d_out, int out_size)
{
    const float* x  = (const float*)d_in[0];
    const float* w0 = (const float*)d_in[1];
    const float* w1 = (const float*)d_in[2];
    const float* w2 = (const float*)d_in[3];
    const float* b0 = (const float*)d_in[4];
    float* out = (float*)d_out;

    cudaFuncSetAttribute(k0_mma, cudaFuncAttributeMaxDynamicSharedMemorySize, K0_SMEM);
    cudaFuncSetAttribute(k1_mma, cudaFuncAttributeMaxDynamicSharedMemorySize, K1_SMEM);
    cudaFuncSetAttribute(k2_mma, cudaFuncAttributeMaxDynamicSharedMemorySize, K2_SMEM);

    k0_mma<<<152, 512, K0_SMEM>>>(x, w0, b0, out);
    k1_mma<<<304, 256, K1_SMEM>>>(x, w1, out);
    k2_mma<<<304, 256, K2_SMEM>>>(x, w2, out);
}